// round 1
// baseline (speedup 1.0000x reference)
#include <cuda_runtime.h>

#define B_SZ 32768
#define DIN_SZ 784
#define D_SZ 256
#define T_SZ 16
#define C_SZ 64

// ---------------- scratch (static __device__, no allocs) ----------------
__device__ float g_h[B_SZ * D_SZ];          // 33.5 MB fp32 h
__device__ int   g_rowlist[T_SZ * B_SZ];    // per-tile row buckets
__device__ int   g_counts[T_SZ];

// ---------------- f32x2 packed-math helpers (Blackwell) -----------------
__device__ __forceinline__ unsigned long long pack2(float lo, float hi) {
    unsigned long long r;
    asm("mov.b64 %0, {%1, %2};" : "=l"(r) : "f"(lo), "f"(hi));
    return r;
}
__device__ __forceinline__ void ffma2(unsigned long long& d,
                                      unsigned long long a,
                                      unsigned long long b) {
    asm("fma.rn.f32x2 %0, %1, %2, %0;" : "+l"(d) : "l"(a), "l"(b));
}
__device__ __forceinline__ float2 unpack2(unsigned long long v) {
    float2 f;
    asm("mov.b64 {%0, %1}, %2;" : "=f"(f.x), "=f"(f.y) : "l"(v));
    return f;
}

__global__ void zero_counts_kernel() {
    if (threadIdx.x < T_SZ) g_counts[threadIdx.x] = 0;
}

// ========================================================================
// Kernel 1: h = x @ Wp + bp  (fused: scores = h@sigs^T, argmax routing,
//           h spill to g_h, rowlist bucketing, tile_indices output)
// BM=64 rows/CTA, full D=256 cols, BK=16, 256 threads (tx32 x ty8), TM=8 TN=8
// ========================================================================
#define BM1 64
#define BK1 16
#define NT1 256

__global__ __launch_bounds__(NT1, 2)
void k1_proj_route(const float* __restrict__ x,
                   const float* __restrict__ Wp,
                   const float* __restrict__ bp,
                   const float* __restrict__ sigs_raw,
                   float* __restrict__ out_idx,
                   int write_idx)
{
    __shared__ float xs[BK1][BM1 + 4];     // x tile, transposed [k][row]
    __shared__ float ws[BK1][D_SZ];        // Wp tile [k][d]
    __shared__ float qs[T_SZ][D_SZ];       // ternary signatures
    __shared__ int   s_cnt[T_SZ];
    __shared__ int   s_base[T_SZ];

    const int tid  = threadIdx.x;
    const int tx   = tid & 31;             // 32 col-groups (8 cols each)
    const int ty   = tid >> 5;             // 8 row-groups  (8 rows each) == warp id
    const int row0 = blockIdx.x * BM1;

    // quantize ternary signatures into smem (once per CTA)
    for (int e = tid; e < T_SZ * D_SZ; e += NT1) {
        float s = sigs_raw[e];
        (&qs[0][0])[e] = (s > 0.3f) ? 1.0f : ((s < -0.3f) ? -1.0f : 0.0f);
    }
    if (tid < T_SZ) s_cnt[tid] = 0;

    unsigned long long acc[8][4];
    #pragma unroll
    for (int i = 0; i < 8; i++)
        #pragma unroll
        for (int j = 0; j < 4; j++) acc[i][j] = 0ull;

    // ---- tile-load thread mapping ----
    // x tile: 64 rows x 16 k = 256 float4; one float4/thread
    const int xr = tid >> 2;               // local row 0..63
    const int xq = tid & 3;                // float4 index within 16-k chunk
    const float4* xg = (const float4*)(x + (long long)(row0 + xr) * DIN_SZ) + xq;
    // Wp tile: 16 k x 256 d = 1024 float4; four float4/thread
    const int wr  = tid >> 6;              // base k row 0..3 (rows wr+4*i)
    const int wc4 = tid & 63;              // float4 col 0..63

    float4 xa;
    float4 wa[4];

    // first tile prefetch
    xa = xg[0];
    #pragma unroll
    for (int i = 0; i < 4; i++)
        wa[i] = ((const float4*)(Wp + (long long)(wr + 4 * i) * D_SZ))[wc4];

    const int NITER = DIN_SZ / BK1;        // 49
    for (int it = 0; it < NITER; it++) {
        // stage tile into smem
        xs[xq * 4 + 0][xr] = xa.x;
        xs[xq * 4 + 1][xr] = xa.y;
        xs[xq * 4 + 2][xr] = xa.z;
        xs[xq * 4 + 3][xr] = xa.w;
        #pragma unroll
        for (int i = 0; i < 4; i++)
            ((float4*)ws[wr + 4 * i])[wc4] = wa[i];
        __syncthreads();

        // prefetch next tile (global loads overlap compute below)
        if (it + 1 < NITER) {
            xa = xg[(it + 1) * 4];
            #pragma unroll
            for (int i = 0; i < 4; i++)
                wa[i] = ((const float4*)(Wp + (long long)((it + 1) * BK1 + wr + 4 * i) * D_SZ))[wc4];
        }

        // compute 16 k-steps, packed f32x2 FMAs
        #pragma unroll
        for (int kk = 0; kk < BK1; kk++) {
            float4 a0 = *(const float4*)&xs[kk][ty * 8];
            float4 a1 = *(const float4*)&xs[kk][ty * 8 + 4];
            const unsigned long long* bq =
                (const unsigned long long*)&ws[kk][tx * 8];
            unsigned long long b0 = bq[0], b1 = bq[1], b2 = bq[2], b3 = bq[3];
            float av[8] = {a0.x, a0.y, a0.z, a0.w, a1.x, a1.y, a1.z, a1.w};
            #pragma unroll
            for (int i = 0; i < 8; i++) {
                unsigned long long a2 = pack2(av[i], av[i]);
                ffma2(acc[i][0], a2, b0);
                ffma2(acc[i][1], a2, b1);
                ffma2(acc[i][2], a2, b2);
                ffma2(acc[i][3], a2, b3);
            }
        }
        __syncthreads();
    }

    // ---- epilogue: bias, unpack, spill h ----
    float4 bpa = ((const float4*)bp)[tx * 2];
    float4 bpb = ((const float4*)bp)[tx * 2 + 1];
    const float bpv[8] = {bpa.x, bpa.y, bpa.z, bpa.w, bpb.x, bpb.y, bpb.z, bpb.w};

    float h[8][8];
    #pragma unroll
    for (int i = 0; i < 8; i++) {
        #pragma unroll
        for (int jp = 0; jp < 4; jp++) {
            float2 v = unpack2(acc[i][jp]);
            h[i][2 * jp]     = v.x + bpv[2 * jp];
            h[i][2 * jp + 1] = v.y + bpv[2 * jp + 1];
        }
        const int r = row0 + ty * 8 + i;
        float4 h0 = make_float4(h[i][0], h[i][1], h[i][2], h[i][3]);
        float4 h1 = make_float4(h[i][4], h[i][5], h[i][6], h[i][7]);
        float4* dst = (float4*)(g_h + (long long)r * D_SZ + tx * 8);
        dst[0] = h0;
        dst[1] = h1;
    }

    // ---- scores + argmax (warp butterfly over tx) ----
    float best[8];
    int   bt[8];
    #pragma unroll
    for (int i = 0; i < 8; i++) { best[i] = -1e30f; bt[i] = 0; }

    for (int t = 0; t < T_SZ; t++) {
        float4 q0 = *(const float4*)&qs[t][tx * 8];
        float4 q1 = *(const float4*)&qs[t][tx * 8 + 4];
        #pragma unroll
        for (int i = 0; i < 8; i++) {
            float p = h[i][0] * q0.x + h[i][1] * q0.y + h[i][2] * q0.z + h[i][3] * q0.w
                    + h[i][4] * q1.x + h[i][5] * q1.y + h[i][6] * q1.z + h[i][7] * q1.w;
            p += __shfl_xor_sync(0xffffffffu, p, 16);
            p += __shfl_xor_sync(0xffffffffu, p, 8);
            p += __shfl_xor_sync(0xffffffffu, p, 4);
            p += __shfl_xor_sync(0xffffffffu, p, 2);
            p += __shfl_xor_sync(0xffffffffu, p, 1);
            // strict > keeps first index on ties (matches jnp.argmax)
            if (p > best[i]) { best[i] = p; bt[i] = t; }
        }
    }

    // ---- CTA-aggregated bucket counting ----
    int lpos[8];
    if (tx == 0) {
        #pragma unroll
        for (int i = 0; i < 8; i++)
            lpos[i] = atomicAdd(&s_cnt[bt[i]], 1);
    }
    __syncthreads();
    if (tid < T_SZ)
        s_base[tid] = atomicAdd(&g_counts[tid], s_cnt[tid]);
    __syncthreads();
    if (tx == 0) {
        #pragma unroll
        for (int i = 0; i < 8; i++) {
            const int r = row0 + ty * 8 + i;
            g_rowlist[bt[i] * B_SZ + s_base[bt[i]] + lpos[i]] = r;
            if (write_idx) out_idx[r] = (float)bt[i];
        }
    }
}

// ========================================================================
// Kernel 2: routed classifier. Tile-grouped GEMM:
//   logits[rows of tile t] = h[rows] @ Wc[t] + bc[t]
// Grid: (256 chunks, 16 tiles). 128 gathered rows/CTA, Wc[t] + h in smem.
// ========================================================================
#define BM2 128
#define NT2 256
#define SMEM2 ((BM2 * D_SZ + D_SZ * C_SZ) * 4)

__global__ __launch_bounds__(NT2, 1)
void k2_classifier(const float* __restrict__ Wc,
                   const float* __restrict__ bc,
                   float* __restrict__ out)
{
    extern __shared__ float sm[];
    float* hs  = sm;                        // [BM2][D_SZ]
    float* wcs = sm + BM2 * D_SZ;           // [D_SZ][C_SZ]
    __shared__ int rid_s[BM2];

    const int t    = blockIdx.y;
    const int cnt  = g_counts[t];
    const int base = blockIdx.x * BM2;
    if (base >= cnt) return;
    const int n = min(BM2, cnt - base);

    const int tid = threadIdx.x;
    if (tid < BM2) {
        int idx = (tid < n) ? tid : (n - 1);   // duplicate last valid row
        rid_s[tid] = g_rowlist[t * B_SZ + base + idx];
    }
    __syncthreads();

    // gather h rows (float4, coalesced within each row)
    for (int e = tid; e < BM2 * (D_SZ / 4); e += NT2) {
        const int lr = e >> 6;
        const int q  = e & 63;
        ((float4*)hs)[lr * (D_SZ / 4) + q] =
            ((const float4*)(g_h + (long long)rid_s[lr] * D_SZ))[q];
    }
    // stage Wc[t]
    const float4* wg = (const float4*)(Wc + (long long)t * D_SZ * C_SZ);
    for (int e = tid; e < D_SZ * (C_SZ / 4); e += NT2)
        ((float4*)wcs)[e] = wg[e];
    __syncthreads();

    const int tx = tid & 15;                // cols tx*4 .. tx*4+3
    const int ty = tid >> 4;                // rows ty*8 .. ty*8+7

    unsigned long long acc[8][2];
    #pragma unroll
    for (int i = 0; i < 8; i++) { acc[i][0] = 0ull; acc[i][1] = 0ull; }

    #pragma unroll 4
    for (int k = 0; k < D_SZ; k++) {
        const unsigned long long* bq =
            (const unsigned long long*)&wcs[k * C_SZ + tx * 4];
        unsigned long long b0 = bq[0], b1 = bq[1];
        #pragma unroll
        for (int i = 0; i < 8; i++) {
            float av = hs[(ty * 8 + i) * D_SZ + k];
            unsigned long long a2 = pack2(av, av);
            ffma2(acc[i][0], a2, b0);
            ffma2(acc[i][1], a2, b1);
        }
    }

    float4 bcv = ((const float4*)(bc + t * C_SZ))[tx];
    #pragma unroll
    for (int i = 0; i < 8; i++) {
        const int lr = ty * 8 + i;
        if (lr < n) {
            float2 v0 = unpack2(acc[i][0]);
            float2 v1 = unpack2(acc[i][1]);
            float4 o = make_float4(v0.x + bcv.x, v0.y + bcv.y,
                                   v1.x + bcv.z, v1.y + bcv.w);
            *(float4*)(out + (long long)rid_s[lr] * C_SZ + tx * 4) = o;
        }
    }
}

// ========================================================================
extern "C" void kernel_launch(void* const* d_in, const int* in_sizes, int n_in,
                              void* d_out, int out_size)
{
    const float* x    = (const float*)d_in[0];
    const float* Wp   = (const float*)d_in[1];
    const float* bp   = (const float*)d_in[2];
    const float* sigs = (const float*)d_in[3];
    const float* Wc   = (const float*)d_in[4];
    const float* bc   = (const float*)d_in[5];
    float* out = (float*)d_out;

    // outputs: logits [B,C] then tile_indices [B] (as output dtype), if present
    const int write_idx = (out_size >= B_SZ * C_SZ + B_SZ) ? 1 : 0;

    (void)in_sizes; (void)n_in;

    zero_counts_kernel<<<1, 32>>>();

    k1_proj_route<<<B_SZ / BM1, NT1>>>(x, Wp, bp, sigs,
                                       out + B_SZ * C_SZ, write_idx);

    cudaFuncSetAttribute(k2_classifier,
                         cudaFuncAttributeMaxDynamicSharedMemorySize, SMEM2);
    dim3 g2(B_SZ / BM2, T_SZ);
    k2_classifier<<<g2, NT2, SMEM2>>>(Wc, bc, out);
}

// round 3
// speedup vs baseline: 1.4475x; 1.4475x over previous
#include <cuda_runtime.h>
#include <cuda_fp16.h>
#include <cstdint>

#define B_SZ 32768
#define DIN_SZ 784
#define D_SZ 256
#define T_SZ 16
#define C_SZ 64
#define NCHUNK 13            // K padded to 832, BK=64
#define NBLK (B_SZ / 128)    // 256 row-blocks

// ---------------- scratch (static __device__, no allocs) ----------------
__device__ float g_h[B_SZ * D_SZ];                // fp32 h (+bias)
__device__ int   g_rowlist[T_SZ * B_SZ];
__device__ int   g_counts[T_SZ];
// pre-converted fp16 hi/lo operand images (swizzled smem-image layout)
__device__ uint4 g_x16[2][NBLK][NCHUNK][1024];    // A: per block 128x64 fp16 (16KB)
__device__ uint4 g_B16[2][NCHUNK][2048];          // B: Wp^T 256x64 fp16 (32KB)

#define XSCALE 16.0f
#define WSCALE 64.0f
#define INVSCALE (1.0f / 1024.0f)

// ---------------- helpers ----------------
__device__ __forceinline__ uint32_t smem_u32(const void* p) {
    uint32_t a;
    asm("{ .reg .u64 t; cvta.to.shared.u64 t, %1; cvt.u32.u64 %0, t; }" : "=r"(a) : "l"(p));
    return a;
}
#define SWZ128(o) ((o) ^ (((o) >> 3) & 0x70))

#define CP_ASYNC16(dst, src) \
    asm volatile("cp.async.cg.shared.global [%0], [%1], 16;" :: "r"(dst), "l"(src))
#define CP_COMMIT() asm volatile("cp.async.commit_group;" ::: "memory")
#define CP_WAIT(n)  asm volatile("cp.async.wait_group %0;" :: "n"(n) : "memory")

__device__ __forceinline__ void ldsm4(uint32_t* r, uint32_t addr) {
    asm volatile("ldmatrix.sync.aligned.m8n8.x4.shared.b16 {%0,%1,%2,%3}, [%4];"
                 : "=r"(r[0]), "=r"(r[1]), "=r"(r[2]), "=r"(r[3]) : "r"(addr));
}
__device__ __forceinline__ void mma16816(float* c, const uint32_t* a, const uint32_t* b) {
    asm volatile("mma.sync.aligned.m16n8k16.row.col.f32.f16.f16.f32 "
                 "{%0,%1,%2,%3}, {%4,%5,%6,%7}, {%8,%9}, {%0,%1,%2,%3};"
                 : "+f"(c[0]), "+f"(c[1]), "+f"(c[2]), "+f"(c[3])
                 : "r"(a[0]), "r"(a[1]), "r"(a[2]), "r"(a[3]), "r"(b[0]), "r"(b[1]));
}

__device__ __forceinline__ uint32_t pack_h2(float a, float b) {
    __half h0 = __float2half_rn(a), h1 = __float2half_rn(b);
    return ((uint32_t)__half_as_ushort(h1) << 16) | __half_as_ushort(h0);
}

// f32x2 helpers (kernel 2)
__device__ __forceinline__ unsigned long long pack2(float lo, float hi) {
    unsigned long long r;
    asm("mov.b64 %0, {%1, %2};" : "=l"(r) : "f"(lo), "f"(hi));
    return r;
}
__device__ __forceinline__ void ffma2(unsigned long long& d, unsigned long long a,
                                      unsigned long long b) {
    asm("fma.rn.f32x2 %0, %1, %2, %0;" : "+l"(d) : "l"(a), "l"(b));
}
__device__ __forceinline__ float2 unpack2(unsigned long long v) {
    float2 f;
    asm("mov.b64 {%0, %1}, %2;" : "=f"(f.x), "=f"(f.y) : "l"(v));
    return f;
}

__global__ void zero_counts_kernel() {
    if (threadIdx.x < T_SZ) g_counts[threadIdx.x] = 0;
}

// ========================================================================
// prep_x: x [32768,784] fp32 -> g_x16 hi/lo fp16 (x16 scaled), swizzled
// block = 8 rows; coalesced gmem reads via smem staging.
// ========================================================================
__global__ __launch_bounds__(256)
void prep_x_kernel(const float* __restrict__ x) {
    __shared__ float xs[8 * 784];
    const int tid = threadIdx.x;
    const int r0  = blockIdx.x * 8;

    // coalesced load 8 rows (contiguous 6272 floats = 1568 float4)
    for (int e = tid; e < 1568; e += 256)
        ((float4*)xs)[e] = ((const float4*)(x + (size_t)r0 * DIN_SZ))[e];
    __syncthreads();

    // tasks: 8 rows x 104 k8-groups (k8 = group of 8 k)
    #pragma unroll
    for (int i = 0; i < 4; i++) {
        const int e = tid + i * 256;
        const int row8 = e >> 7;
        const int k8   = e & 127;
        if (k8 >= 104) continue;
        float v[8];
        #pragma unroll
        for (int j = 0; j < 8; j++) {
            const int k = k8 * 8 + j;
            v[j] = (k < DIN_SZ) ? xs[row8 * DIN_SZ + k] * XSCALE : 0.0f;
        }
        uint4 hi, lo;
        float h[8];
        #pragma unroll
        for (int j = 0; j < 8; j++) h[j] = __half2float(__float2half_rn(v[j]));
        hi.x = pack_h2(v[0], v[1]); hi.y = pack_h2(v[2], v[3]);
        hi.z = pack_h2(v[4], v[5]); hi.w = pack_h2(v[6], v[7]);
        lo.x = pack_h2(v[0] - h[0], v[1] - h[1]); lo.y = pack_h2(v[2] - h[2], v[3] - h[3]);
        lo.z = pack_h2(v[4] - h[4], v[5] - h[5]); lo.w = pack_h2(v[6] - h[6], v[7] - h[7]);

        const int row = r0 + row8;
        const int blk = row >> 7;
        const int ci  = k8 >> 3;
        const uint32_t off = SWZ128((uint32_t)((row & 127) * 128 + (k8 & 7) * 16));
        g_x16[0][blk][ci][off >> 4] = hi;
        g_x16[1][blk][ci][off >> 4] = lo;
    }
}

// ========================================================================
// prep_B: Wp [784,256] -> g_B16: Wp^T hi/lo fp16 (x64 scaled), swizzled
// grid = NCHUNK blocks of 256 threads; task = (n, k8local)
// ========================================================================
__global__ __launch_bounds__(256)
void prep_B_kernel(const float* __restrict__ Wp) {
    const int ci  = blockIdx.x;
    const int tid = threadIdx.x;
    #pragma unroll
    for (int i = 0; i < 8; i++) {
        const int e   = tid + i * 256;      // 0..2047
        const int n   = e >> 3;
        const int k8l = e & 7;
        float v[8], h[8];
        #pragma unroll
        for (int j = 0; j < 8; j++) {
            const int k = ci * 64 + k8l * 8 + j;
            v[j] = (k < DIN_SZ) ? Wp[(size_t)k * D_SZ + n] * WSCALE : 0.0f;
            h[j] = __half2float(__float2half_rn(v[j]));
        }
        uint4 hi, lo;
        hi.x = pack_h2(v[0], v[1]); hi.y = pack_h2(v[2], v[3]);
        hi.z = pack_h2(v[4], v[5]); hi.w = pack_h2(v[6], v[7]);
        lo.x = pack_h2(v[0] - h[0], v[1] - h[1]); lo.y = pack_h2(v[2] - h[2], v[3] - h[3]);
        lo.z = pack_h2(v[4] - h[4], v[5] - h[5]); lo.w = pack_h2(v[6] - h[6], v[7] - h[7]);
        const uint32_t off = SWZ128((uint32_t)(n * 128 + k8l * 16));
        g_B16[0][ci][off >> 4] = hi;
        g_B16[1][ci][off >> 4] = lo;
    }
}

// ========================================================================
// Kernel 1: h = x@Wp + bp via mma.sync fp16 3-product split.
// CTA 128x256, 8 warps (2x4), warp tile 64x64, BK=64, 2-stage cp.async.
// Epilogue: bias+unscale -> smem h; scores+argmax; bucket; spill g_h.
// ========================================================================
#define NT1 256
#define SMEM1 196608   // As 2x2x16KB (64KB) + Bs 2x2x32KB (128KB)
#define HSTRIDE 260

__global__ __launch_bounds__(NT1)
void k1_proj_route(const float* __restrict__ bp,
                   const float* __restrict__ sigs_raw,
                   float* __restrict__ out_idx,
                   int write_idx)
{
    extern __shared__ char sm[];
    __shared__ float q_s[T_SZ][D_SZ];
    __shared__ float bp_s[D_SZ];
    __shared__ float part[128][T_SZ];
    __shared__ int s_cnt[T_SZ];
    __shared__ int s_base[T_SZ];

    const int tid  = threadIdx.x;
    const int lane = tid & 31;
    const int wid  = tid >> 5;
    const int wm   = wid >> 2;      // 0..1
    const int wn   = wid & 3;       // 0..3
    const int blk  = blockIdx.x;
    const int row0 = blk * 128;

    const uint32_t As_u = smem_u32(sm);
    const uint32_t Bs_u = As_u + 65536;

    // quantize signatures + bias into smem (overlaps pipeline prologue)
    for (int e = tid; e < T_SZ * D_SZ; e += NT1) {
        float s = sigs_raw[e];
        (&q_s[0][0])[e] = (s > 0.3f) ? 1.0f : ((s < -0.3f) ? -1.0f : 0.0f);
    }
    bp_s[tid] = bp[tid];
    if (tid < T_SZ) s_cnt[tid] = 0;

    // ---- cp.async issue for chunk ci into stage st ----
    auto issue = [&](int ci, int st) {
        #pragma unroll
        for (int i = 0; i < 8; i++) {
            const int e = tid + i * 256;
            const int sp = e >> 10, g = e & 1023;
            CP_ASYNC16(As_u + st * 32768 + sp * 16384 + g * 16,
                       (const void*)&g_x16[sp][blk][ci][g]);
        }
        #pragma unroll
        for (int i = 0; i < 16; i++) {
            const int e = tid + i * 256;
            const int sp = e >> 11, g = e & 2047;
            CP_ASYNC16(Bs_u + st * 65536 + sp * 32768 + g * 16,
                       (const void*)&g_B16[sp][ci][g]);
        }
        CP_COMMIT();
    };

    issue(0, 0);
    issue(1, 1);

    // ldmatrix lane offsets (bytes, pre-swizzle)
    uint32_t a_off[4], b_off[4];
    #pragma unroll
    for (int mt = 0; mt < 4; mt++)
        a_off[mt] = (uint32_t)((wm * 64 + mt * 16 + (lane & 15)) * 128 + (lane >> 4) * 16);
    #pragma unroll
    for (int np = 0; np < 4; np++) {
        const int bn = wn * 64 + np * 16 + ((lane >> 4) << 3) + (lane & 7);
        b_off[np] = (uint32_t)(bn * 128 + ((lane >> 3) & 1) * 16);
    }

    float acc[4][8][4];
    #pragma unroll
    for (int mt = 0; mt < 4; mt++)
        #pragma unroll
        for (int n8 = 0; n8 < 8; n8++)
            #pragma unroll
            for (int c = 0; c < 4; c++) acc[mt][n8][c] = 0.0f;

    for (int ci = 0; ci < NCHUNK; ci++) {
        const int st = ci & 1;
        if (ci == NCHUNK - 1) { CP_WAIT(0); } else { CP_WAIT(1); }
        __syncthreads();

        const uint32_t a_hi = As_u + st * 32768;
        const uint32_t a_lo = a_hi + 16384;
        const uint32_t b_hi = Bs_u + st * 65536;
        const uint32_t b_lo = b_hi + 32768;

        #pragma unroll
        for (int ks = 0; ks < 4; ks++) {
            uint32_t ah[4][4], al[4][4];
            #pragma unroll
            for (int mt = 0; mt < 4; mt++) {
                const uint32_t off = SWZ128(a_off[mt] + ks * 32);
                ldsm4(ah[mt], a_hi + off);
                ldsm4(al[mt], a_lo + off);
            }
            uint32_t bh[8][2];
            #pragma unroll
            for (int np = 0; np < 4; np++) {
                const uint32_t off = SWZ128(b_off[np] + ks * 32);
                uint32_t r[4];
                ldsm4(r, b_hi + off);
                bh[np * 2][0] = r[0]; bh[np * 2][1] = r[1];
                bh[np * 2 + 1][0] = r[2]; bh[np * 2 + 1][1] = r[3];
            }
            #pragma unroll
            for (int mt = 0; mt < 4; mt++)
                #pragma unroll
                for (int n8 = 0; n8 < 8; n8++)
                    mma16816(acc[mt][n8], ah[mt], bh[n8]);
            #pragma unroll
            for (int mt = 0; mt < 4; mt++)
                #pragma unroll
                for (int n8 = 0; n8 < 8; n8++)
                    mma16816(acc[mt][n8], al[mt], bh[n8]);
            uint32_t bl[8][2];
            #pragma unroll
            for (int np = 0; np < 4; np++) {
                const uint32_t off = SWZ128(b_off[np] + ks * 32);
                uint32_t r[4];
                ldsm4(r, b_lo + off);
                bl[np * 2][0] = r[0]; bl[np * 2][1] = r[1];
                bl[np * 2 + 1][0] = r[2]; bl[np * 2 + 1][1] = r[3];
            }
            #pragma unroll
            for (int mt = 0; mt < 4; mt++)
                #pragma unroll
                for (int n8 = 0; n8 < 8; n8++)
                    mma16816(acc[mt][n8], ah[mt], bl[n8]);
        }
        __syncthreads();
        if (ci + 2 < NCHUNK) issue(ci + 2, st);
    }

    // ---- epilogue: fragments -> smem h (bias + unscale) ----
    __syncthreads();   // all warps done with smem tiles
    float* hsm = (float*)sm;
    #pragma unroll
    for (int mt = 0; mt < 4; mt++) {
        const int r_a = wm * 64 + mt * 16 + (lane >> 2);
        #pragma unroll
        for (int n8 = 0; n8 < 8; n8++) {
            const int col = wn * 64 + n8 * 8 + (lane & 3) * 2;
            float2 v01, v23;
            v01.x = acc[mt][n8][0] * INVSCALE + bp_s[col];
            v01.y = acc[mt][n8][1] * INVSCALE + bp_s[col + 1];
            v23.x = acc[mt][n8][2] * INVSCALE + bp_s[col];
            v23.y = acc[mt][n8][3] * INVSCALE + bp_s[col + 1];
            *(float2*)&hsm[r_a * HSTRIDE + col]       = v01;
            *(float2*)&hsm[(r_a + 8) * HSTRIDE + col] = v23;
        }
    }
    __syncthreads();

    // ---- spill h to g_h (coalesced) ----
    #pragma unroll
    for (int i = 0; i < 32; i++) {
        const int e = tid + i * 256;
        const int row = e >> 6, c4 = e & 63;
        float4 v = *(const float4*)&hsm[row * HSTRIDE + c4 * 4];
        *(float4*)&g_h[(size_t)(row0 + row) * D_SZ + c4 * 4] = v;
    }

    // ---- scores: thread (r, half) covers 128 cols ----
    const int r    = tid >> 1;
    const int half = tid & 1;
    float sc[T_SZ];
    #pragma unroll
    for (int t = 0; t < T_SZ; t++) sc[t] = 0.0f;
    const float* hrow = &hsm[r * HSTRIDE + half * 128];
    #pragma unroll 4
    for (int j = 0; j < 32; j++) {
        const float4 hv = ((const float4*)hrow)[j];
        #pragma unroll
        for (int t = 0; t < T_SZ; t++) {
            const float4 qv = ((const float4*)&q_s[t][half * 128])[j];
            sc[t] += hv.x * qv.x + hv.y * qv.y + hv.z * qv.z + hv.w * qv.w;
        }
    }
    if (half == 0) {
        #pragma unroll
        for (int t = 0; t < T_SZ; t++) part[r][t] = sc[t];
    }
    __syncthreads();

    int bt = 0;
    if (half == 1) {
        float best = -1e30f;
        #pragma unroll
        for (int t = 0; t < T_SZ; t++) {
            const float s = sc[t] + part[r][t];
            if (s > best) { best = s; bt = t; }
        }
    }
    int lpos = 0;
    if (half == 1) lpos = atomicAdd(&s_cnt[bt], 1);
    __syncthreads();
    if (tid < T_SZ) s_base[tid] = atomicAdd(&g_counts[tid], s_cnt[tid]);
    __syncthreads();
    if (half == 1) {
        g_rowlist[bt * B_SZ + s_base[bt] + lpos] = row0 + r;
        if (write_idx) out_idx[row0 + r] = (float)bt;
    }
}

// ========================================================================
// Kernel 2: routed classifier (fp32 f32x2), unchanged from R1
// ========================================================================
#define BM2 128
#define NT2 256
#define SMEM2 ((BM2 * D_SZ + D_SZ * C_SZ) * 4)

__global__ __launch_bounds__(NT2, 1)
void k2_classifier(const float* __restrict__ Wc,
                   const float* __restrict__ bc,
                   float* __restrict__ out)
{
    extern __shared__ float smf[];
    float* hs  = smf;
    float* wcs = smf + BM2 * D_SZ;
    __shared__ int rid_s[BM2];

    const int t    = blockIdx.y;
    const int cnt  = g_counts[t];
    const int base = blockIdx.x * BM2;
    if (base >= cnt) return;
    const int n = min(BM2, cnt - base);

    const int tid = threadIdx.x;
    if (tid < BM2) {
        int idx = (tid < n) ? tid : (n - 1);
        rid_s[tid] = g_rowlist[t * B_SZ + base + idx];
    }
    __syncthreads();

    for (int e = tid; e < BM2 * (D_SZ / 4); e += NT2) {
        const int lr = e >> 6;
        const int q  = e & 63;
        ((float4*)hs)[lr * (D_SZ / 4) + q] =
            ((const float4*)(g_h + (size_t)rid_s[lr] * D_SZ))[q];
    }
    const float4* wg = (const float4*)(Wc + (size_t)t * D_SZ * C_SZ);
    for (int e = tid; e < D_SZ * (C_SZ / 4); e += NT2)
        ((float4*)wcs)[e] = wg[e];
    __syncthreads();

    const int tx = tid & 15;
    const int ty = tid >> 4;

    unsigned long long acc[8][2];
    #pragma unroll
    for (int i = 0; i < 8; i++) { acc[i][0] = 0ull; acc[i][1] = 0ull; }

    #pragma unroll 4
    for (int k = 0; k < D_SZ; k++) {
        const unsigned long long* bq = (const unsigned long long*)&wcs[k * C_SZ + tx * 4];
        unsigned long long b0 = bq[0], b1 = bq[1];
        #pragma unroll
        for (int i = 0; i < 8; i++) {
            float av = hs[(ty * 8 + i) * D_SZ + k];
            unsigned long long a2 = pack2(av, av);
            ffma2(acc[i][0], a2, b0);
            ffma2(acc[i][1], a2, b1);
        }
    }

    float4 bcv = ((const float4*)(bc + t * C_SZ))[tx];
    #pragma unroll
    for (int i = 0; i < 8; i++) {
        const int lr = ty * 8 + i;
        if (lr < n) {
            float2 v0 = unpack2(acc[i][0]);
            float2 v1 = unpack2(acc[i][1]);
            float4 o = make_float4(v0.x + bcv.x, v0.y + bcv.y, v1.x + bcv.z, v1.y + bcv.w);
            *(float4*)(out + (size_t)rid_s[lr] * C_SZ + tx * 4) = o;
        }
    }
}

// ========================================================================
extern "C" void kernel_launch(void* const* d_in, const int* in_sizes, int n_in,
                              void* d_out, int out_size)
{
    const float* x    = (const float*)d_in[0];
    const float* Wp   = (const float*)d_in[1];
    const float* bp   = (const float*)d_in[2];
    const float* sigs = (const float*)d_in[3];
    const float* Wc   = (const float*)d_in[4];
    const float* bc   = (const float*)d_in[5];
    float* out = (float*)d_out;

    const int write_idx = (out_size >= B_SZ * C_SZ + B_SZ) ? 1 : 0;
    (void)in_sizes; (void)n_in;

    zero_counts_kernel<<<1, 32>>>();
    prep_x_kernel<<<B_SZ / 8, 256>>>(x);
    prep_B_kernel<<<NCHUNK, 256>>>(Wp);

    cudaFuncSetAttribute(k1_proj_route, cudaFuncAttributeMaxDynamicSharedMemorySize, SMEM1);
    k1_proj_route<<<NBLK, NT1, SMEM1>>>(bp, sigs, out + B_SZ * C_SZ, write_idx);

    cudaFuncSetAttribute(k2_classifier, cudaFuncAttributeMaxDynamicSharedMemorySize, SMEM2);
    dim3 g2(B_SZ / BM2, T_SZ);
    k2_classifier<<<g2, NT2, SMEM2>>>(Wc, bc, out);
}

// round 4
// speedup vs baseline: 1.8116x; 1.2515x over previous
#include <cuda_runtime.h>
#include <cuda_fp16.h>
#include <cstdint>

#define B_SZ 32768
#define DIN_SZ 784
#define D_SZ 256
#define T_SZ 16
#define C_SZ 64
#define NCHUNK 13            // K padded to 832, BK=64
#define NBLK (B_SZ / 128)

// ---------------- scratch (static __device__, no allocs) ----------------
__device__ float g_h[B_SZ * D_SZ];
__device__ int   g_rowlist[T_SZ * B_SZ];
__device__ int   g_counts[T_SZ];
__device__ uint4 g_B16[2][NCHUNK][2048];     // Wp^T hi/lo fp16 swizzled (32KB/chunk/split)
__device__ uint4 g_Ws16[2][NCHUNK][128];     // Ws^T hi/lo fp16 swizzled (2KB/chunk/split)
__device__ float g_bs[T_SZ];                 // 1024 * (bp @ q(sigs)^T)

#define XSCALE 16.0f
#define WSCALE 64.0f
#define INVSCALE (1.0f / 1024.0f)

// ---------------- helpers ----------------
__device__ __forceinline__ uint32_t smem_u32(const void* p) {
    uint32_t a;
    asm("{ .reg .u64 t; cvta.to.shared.u64 t, %1; cvt.u32.u64 %0, t; }" : "=r"(a) : "l"(p));
    return a;
}
#define SWZ128(o) ((o) ^ (((o) >> 3) & 0x70))

#define CP_ASYNC16(dst, src) \
    asm volatile("cp.async.cg.shared.global [%0], [%1], 16;" :: "r"(dst), "l"(src))
#define CP_COMMIT() asm volatile("cp.async.commit_group;" ::: "memory")
#define CP_WAIT(n)  asm volatile("cp.async.wait_group %0;" :: "n"(n) : "memory")

__device__ __forceinline__ void ldsm4(uint32_t* r, uint32_t addr) {
    asm volatile("ldmatrix.sync.aligned.m8n8.x4.shared.b16 {%0,%1,%2,%3}, [%4];"
                 : "=r"(r[0]), "=r"(r[1]), "=r"(r[2]), "=r"(r[3]) : "r"(addr));
}
__device__ __forceinline__ void mma16816(float* c, const uint32_t* a, const uint32_t* b) {
    asm volatile("mma.sync.aligned.m16n8k16.row.col.f32.f16.f16.f32 "
                 "{%0,%1,%2,%3}, {%4,%5,%6,%7}, {%8,%9}, {%0,%1,%2,%3};"
                 : "+f"(c[0]), "+f"(c[1]), "+f"(c[2]), "+f"(c[3])
                 : "r"(a[0]), "r"(a[1]), "r"(a[2]), "r"(a[3]), "r"(b[0]), "r"(b[1]));
}
__device__ __forceinline__ uint32_t pack_h2(float a, float b) {
    __half h0 = __float2half_rn(a), h1 = __float2half_rn(b);
    return ((uint32_t)__half_as_ushort(h1) << 16) | __half_as_ushort(h0);
}

// f32x2 helpers (kernel 2)
__device__ __forceinline__ unsigned long long pack2(float lo, float hi) {
    unsigned long long r;
    asm("mov.b64 %0, {%1, %2};" : "=l"(r) : "f"(lo), "f"(hi));
    return r;
}
__device__ __forceinline__ void ffma2(unsigned long long& d, unsigned long long a,
                                      unsigned long long b) {
    asm("fma.rn.f32x2 %0, %1, %2, %0;" : "+l"(d) : "l"(a), "l"(b));
}
__device__ __forceinline__ float2 unpack2(unsigned long long v) {
    float2 f;
    asm("mov.b64 {%0, %1}, %2;" : "=f"(f.x), "=f"(f.y) : "l"(v));
    return f;
}

__global__ void zero_counts_kernel() {
    if (threadIdx.x < T_SZ) g_counts[threadIdx.x] = 0;
}

// ========================================================================
// prep_B: Wp [784,256] -> g_B16 hi/lo fp16 (x64), transposed + swizzled
// ========================================================================
__global__ __launch_bounds__(256)
void prep_B_kernel(const float* __restrict__ Wp) {
    const int ci  = blockIdx.x;
    const int tid = threadIdx.x;
    #pragma unroll
    for (int i = 0; i < 8; i++) {
        const int e   = tid + i * 256;
        const int n   = e >> 3;
        const int k8l = e & 7;
        float v[8], h[8];
        #pragma unroll
        for (int j = 0; j < 8; j++) {
            const int k = ci * 64 + k8l * 8 + j;
            v[j] = (k < DIN_SZ) ? Wp[(size_t)k * D_SZ + n] * WSCALE : 0.0f;
            h[j] = __half2float(__float2half_rn(v[j]));
        }
        uint4 hi, lo;
        hi.x = pack_h2(v[0], v[1]); hi.y = pack_h2(v[2], v[3]);
        hi.z = pack_h2(v[4], v[5]); hi.w = pack_h2(v[6], v[7]);
        lo.x = pack_h2(v[0] - h[0], v[1] - h[1]); lo.y = pack_h2(v[2] - h[2], v[3] - h[3]);
        lo.z = pack_h2(v[4] - h[4], v[5] - h[5]); lo.w = pack_h2(v[6] - h[6], v[7] - h[7]);
        const uint32_t off = SWZ128((uint32_t)(n * 128 + k8l * 16));
        g_B16[0][ci][off >> 4] = hi;
        g_B16[1][ci][off >> 4] = lo;
    }
}

// ========================================================================
// prep_Ws: Ws[k][t] = sum_d Wp[k][d]*q(sigs)[t][d] -> hi/lo fp16 swizzled;
//          g_bs[t] = 1024 * bp @ q^T
// grid 104 x 128 threads: block = 8 k rows, thread = (k_local, t)
// ========================================================================
__global__ __launch_bounds__(128)
void prep_Ws_kernel(const float* __restrict__ Wp,
                    const float* __restrict__ bp,
                    const float* __restrict__ sigs_raw) {
    __shared__ float q_s[T_SZ][257];
    __shared__ float w_s[8][257];
    const int tid = threadIdx.x;
    const int k0  = blockIdx.x * 8;

    for (int e = tid; e < T_SZ * D_SZ; e += 128) {
        const int t = e >> 8, d = e & 255;
        float s = sigs_raw[e];
        q_s[t][d] = (s > 0.3f) ? 1.0f : ((s < -0.3f) ? -1.0f : 0.0f);
    }
    for (int e = tid; e < 8 * D_SZ; e += 128) {
        const int r = e >> 8, d = e & 255;
        const int k = k0 + r;
        w_s[r][d] = (k < DIN_SZ) ? Wp[(size_t)k * D_SZ + d] : 0.f;
    }
    __syncthreads();

    const int ty = tid >> 4;
    const int t  = tid & 15;
    const int k  = k0 + ty;
    float acc = 0.f;
    #pragma unroll 8
    for (int d = 0; d < D_SZ; d++) acc += w_s[ty][d] * q_s[t][d];

    acc *= WSCALE;
    __half hi = __float2half_rn(acc);
    __half lo = __float2half_rn(acc - __half2float(hi));
    const int ci = k >> 6, kin = k & 63;
    const uint32_t off = SWZ128((uint32_t)(t * 128 + kin * 2));
    *(unsigned short*)((char*)g_Ws16[0][ci] + off) = __half_as_ushort(hi);
    *(unsigned short*)((char*)g_Ws16[1][ci] + off) = __half_as_ushort(lo);

    if (blockIdx.x == 0 && tid < T_SZ) {
        float a = 0.f;
        for (int d = 0; d < D_SZ; d++) a += bp[d] * q_s[tid][d];
        g_bs[tid] = a * (XSCALE * WSCALE);
    }
}

// ========================================================================
// Kernel 1: fused x-convert + 2-product h GEMM + 3-product N=16 score strip
// CTA 128x256, 8 warps (2x4), warp tile 64x64, BK=64, double-buffered.
// smem: A hi/lo 2st x 32KB | B hi/lo 2st x 64KB | Ws 2st x 4KB = 204800 B
// ========================================================================
#define NT1 256
#define SMEM1 204800
#define HSTRIDE 260
#define A_ST(st, sp) ((st) * 32768 + (sp) * 16384)
#define B_ST(st, sp) (65536 + (st) * 65536 + (sp) * 32768)
#define W_ST(st, sp) (196608 + (st) * 4096 + (sp) * 2048)

__global__ __launch_bounds__(NT1)
void k1_proj_route(const float* __restrict__ x,
                   const float* __restrict__ bp,
                   float* __restrict__ out_idx,
                   int write_idx)
{
    extern __shared__ char sm[];
    __shared__ float bp_s[D_SZ];
    __shared__ float sb_s[T_SZ];
    __shared__ int s_cnt[T_SZ];
    __shared__ int s_base[T_SZ];

    const int tid  = threadIdx.x;
    const int lane = tid & 31;
    const int wid  = tid >> 5;
    const int wm   = wid >> 2;
    const int wn   = wid & 3;
    const int row0 = blockIdx.x * 128;

    const uint32_t smb = smem_u32(sm);

    bp_s[tid] = bp[tid];
    if (tid < T_SZ) { s_cnt[tid] = 0; sb_s[tid] = g_bs[tid]; }

    // ---- x load half (4 float4) ----
    const int xrow = tid >> 4;           // shared by e-mapping below
    auto ldgA = [&](int ci, int h, float4* xr) {
        #pragma unroll
        for (int i = 0; i < 4; i++) {
            const int e   = (h * 4 + i) * 256 + tid;
            const int row = e >> 4;
            const int q4  = e & 15;
            float4 v = make_float4(0.f, 0.f, 0.f, 0.f);
            if (ci < 12 || q4 < 4)
                v = *(const float4*)(x + (size_t)(row0 + row) * DIN_SZ + ci * 64 + q4 * 4);
            xr[i] = v;
        }
    };
    auto stsA = [&](int h, int st, const float4* xr) {
        #pragma unroll
        for (int i = 0; i < 4; i++) {
            const int e   = (h * 4 + i) * 256 + tid;
            const int row = e >> 4;
            const int q4  = e & 15;
            float vx = xr[i].x * XSCALE, vy = xr[i].y * XSCALE;
            float vz = xr[i].z * XSCALE, vw = xr[i].w * XSCALE;
            __half h0 = __float2half_rn(vx), h1 = __float2half_rn(vy);
            __half h2 = __float2half_rn(vz), h3 = __float2half_rn(vw);
            uint2 hv, lv;
            hv.x = ((uint32_t)__half_as_ushort(h1) << 16) | __half_as_ushort(h0);
            hv.y = ((uint32_t)__half_as_ushort(h3) << 16) | __half_as_ushort(h2);
            lv.x = pack_h2(vx - __half2float(h0), vy - __half2float(h1));
            lv.y = pack_h2(vz - __half2float(h2), vw - __half2float(h3));
            const uint32_t off = SWZ128((uint32_t)(row * 128 + q4 * 8));
            *(uint2*)(sm + A_ST(st, 0) + off) = hv;
            *(uint2*)(sm + A_ST(st, 1) + off) = lv;
        }
    };
    auto issueB = [&](int ci, int st) {
        #pragma unroll
        for (int i = 0; i < 16; i++) {
            const int e = tid + i * 256;
            const int sp = e >> 11, g = e & 2047;
            CP_ASYNC16(smb + B_ST(st, sp) + g * 16, (const void*)&g_B16[sp][ci][g]);
        }
        {
            const int sp = tid >> 7, g = tid & 127;
            CP_ASYNC16(smb + W_ST(st, sp) + g * 16, (const void*)&g_Ws16[sp][ci][g]);
        }
        CP_COMMIT();
    };

    // ---- fragment lane offsets (bytes, pre-swizzle) ----
    uint32_t a_off[4], b_off[4];
    #pragma unroll
    for (int mt = 0; mt < 4; mt++)
        a_off[mt] = (uint32_t)((wm * 64 + mt * 16 + (lane & 15)) * 128 + (lane >> 4) * 16);
    #pragma unroll
    for (int np = 0; np < 4; np++) {
        const int bn = wn * 64 + np * 16 + ((lane >> 4) << 3) + (lane & 7);
        b_off[np] = (uint32_t)(bn * 128 + ((lane >> 3) & 1) * 16);
    }
    // strip offsets: warp wid<4 owns strip rows wid*32 .. wid*32+31
    uint32_t sa_off[2], sl_off[2], ws_off;
    const int sbase = wid * 32;
    #pragma unroll
    for (int t = 0; t < 2; t++) {
        sa_off[t] = (uint32_t)((sbase + t * 16 + (lane & 15)) * 128 + (lane >> 4) * 16);
        sl_off[t] = sa_off[t];
    }
    ws_off = (uint32_t)((((lane >> 4) << 3) + (lane & 7)) * 128 + ((lane >> 3) & 1) * 16);

    float acc[4][8][4];
    #pragma unroll
    for (int mt = 0; mt < 4; mt++)
        #pragma unroll
        for (int n8 = 0; n8 < 8; n8++)
            #pragma unroll
            for (int c = 0; c < 4; c++) acc[mt][n8][c] = 0.0f;
    float sacc[2][2][4];
    #pragma unroll
    for (int mt = 0; mt < 2; mt++)
        #pragma unroll
        for (int n8 = 0; n8 < 2; n8++)
            #pragma unroll
            for (int c = 0; c < 4; c++) sacc[mt][n8][c] = 0.0f;

    // ---- prologue ----
    issueB(0, 0);
    issueB(1, 1);
    {
        float4 xr[4];
        ldgA(0, 0, xr); stsA(0, 0, xr);
        ldgA(0, 1, xr); stsA(1, 0, xr);
    }
    CP_WAIT(1);
    __syncthreads();

    // ---- main loop ----
    for (int ci = 0; ci < NCHUNK; ci++) {
        const int st = ci & 1;
        const bool nx = (ci + 1 < NCHUNK);
        const uint32_t a_hi = smb + A_ST(st, 0);
        const uint32_t a_lo = smb + A_ST(st, 1);
        const uint32_t b_hi = smb + B_ST(st, 0);
        const uint32_t b_lo = smb + B_ST(st, 1);
        const uint32_t w_hi = smb + W_ST(st, 0);
        const uint32_t w_lo = smb + W_ST(st, 1);

        float4 xr[4];
        if (nx) ldgA(ci + 1, 0, xr);

        #pragma unroll
        for (int ks = 0; ks < 4; ks++) {
            uint32_t ah[4][4];
            #pragma unroll
            for (int mt = 0; mt < 4; mt++)
                ldsm4(ah[mt], a_hi + SWZ128(a_off[mt] + ks * 32));
            uint32_t bh[8][2];
            #pragma unroll
            for (int np = 0; np < 4; np++) {
                uint32_t r[4];
                ldsm4(r, b_hi + SWZ128(b_off[np] + ks * 32));
                bh[np * 2][0] = r[0]; bh[np * 2][1] = r[1];
                bh[np * 2 + 1][0] = r[2]; bh[np * 2 + 1][1] = r[3];
            }
            #pragma unroll
            for (int mt = 0; mt < 4; mt++)
                #pragma unroll
                for (int n8 = 0; n8 < 8; n8++)
                    mma16816(acc[mt][n8], ah[mt], bh[n8]);
            uint32_t bl[8][2];
            #pragma unroll
            for (int np = 0; np < 4; np++) {
                uint32_t r[4];
                ldsm4(r, b_lo + SWZ128(b_off[np] + ks * 32));
                bl[np * 2][0] = r[0]; bl[np * 2][1] = r[1];
                bl[np * 2 + 1][0] = r[2]; bl[np * 2 + 1][1] = r[3];
            }
            #pragma unroll
            for (int mt = 0; mt < 4; mt++)
                #pragma unroll
                for (int n8 = 0; n8 < 8; n8++)
                    mma16816(acc[mt][n8], bl == bl ? ah[mt] : ah[mt], bl[n8]);

            // ---- score strip (warps 0-3 only) ----
            if (wid < 4) {
                uint32_t sah[2][4], sal[2][4];
                if (wid < 2) {
                    // strip rows coincide with this warp's ah tiles
                    #pragma unroll
                    for (int t = 0; t < 2; t++)
                        #pragma unroll
                        for (int c = 0; c < 4; c++) sah[t][c] = ah[wid * 2 + t][c];
                } else {
                    #pragma unroll
                    for (int t = 0; t < 2; t++)
                        ldsm4(sah[t], a_hi + SWZ128(sa_off[t] + ks * 32));
                }
                #pragma unroll
                for (int t = 0; t < 2; t++)
                    ldsm4(sal[t], a_lo + SWZ128(sl_off[t] + ks * 32));
                uint32_t wsh[2][2], wsl[2][2];
                {
                    uint32_t r[4];
                    ldsm4(r, w_hi + SWZ128(ws_off + ks * 32));
                    wsh[0][0] = r[0]; wsh[0][1] = r[1]; wsh[1][0] = r[2]; wsh[1][1] = r[3];
                    ldsm4(r, w_lo + SWZ128(ws_off + ks * 32));
                    wsl[0][0] = r[0]; wsl[0][1] = r[1]; wsl[1][0] = r[2]; wsl[1][1] = r[3];
                }
                #pragma unroll
                for (int mt = 0; mt < 2; mt++)
                    #pragma unroll
                    for (int n8 = 0; n8 < 2; n8++) {
                        mma16816(sacc[mt][n8], sah[mt], wsh[n8]);
                        mma16816(sacc[mt][n8], sah[mt], wsl[n8]);
                        mma16816(sacc[mt][n8], sal[mt], wsh[n8]);
                    }
            }

            if (ks == 1 && nx) { stsA(0, st ^ 1, xr); ldgA(ci + 1, 1, xr); }
        }
        if (nx) stsA(1, st ^ 1, xr);

        __syncthreads();
        if (ci + 2 < NCHUNK) issueB(ci + 2, st);
        if (nx) { CP_WAIT(1); __syncthreads(); }
    }

    __syncthreads();   // done with operand smem; reuse for h staging

    // ---- epilogue: h fragments -> smem (bias + unscale) ----
    float* hsm = (float*)sm;
    #pragma unroll
    for (int mt = 0; mt < 4; mt++) {
        const int r_a = wm * 64 + mt * 16 + (lane >> 2);
        #pragma unroll
        for (int n8 = 0; n8 < 8; n8++) {
            const int col = wn * 64 + n8 * 8 + (lane & 3) * 2;
            float2 v01, v23;
            v01.x = acc[mt][n8][0] * INVSCALE + bp_s[col];
            v01.y = acc[mt][n8][1] * INVSCALE + bp_s[col + 1];
            v23.x = acc[mt][n8][2] * INVSCALE + bp_s[col];
            v23.y = acc[mt][n8][3] * INVSCALE + bp_s[col + 1];
            *(float2*)&hsm[r_a * HSTRIDE + col]       = v01;
            *(float2*)&hsm[(r_a + 8) * HSTRIDE + col] = v23;
        }
    }

    // ---- strip argmax (warps 0-3; rows wid*32..wid*32+31) ----
    int   my_bt[4];
    int   my_row[4];
    bool  writer = (wid < 4) && ((lane & 3) == 0);
    if (wid < 4) {
        float sb0 = sb_s[(lane & 3) * 2];
        float sb1 = sb_s[(lane & 3) * 2 + 1];
        float sb2 = sb_s[(lane & 3) * 2 + 8];
        float sb3 = sb_s[(lane & 3) * 2 + 9];
        #pragma unroll
        for (int mt = 0; mt < 2; mt++) {
            #pragma unroll
            for (int hf = 0; hf < 2; hf++) {
                float v0 = sacc[mt][0][hf * 2]     + sb0;
                float v1 = sacc[mt][0][hf * 2 + 1] + sb1;
                float v2 = sacc[mt][1][hf * 2]     + sb2;
                float v3 = sacc[mt][1][hf * 2 + 1] + sb3;
                int c0 = (lane & 3) * 2;
                float bv = v0; int bi = c0;
                if (v1 > bv) { bv = v1; bi = c0 + 1; }
                if (v2 > bv) { bv = v2; bi = c0 + 8; }
                if (v3 > bv) { bv = v3; bi = c0 + 9; }
                #pragma unroll
                for (int d = 1; d <= 2; d <<= 1) {
                    float ov = __shfl_xor_sync(0xffffffffu, bv, d);
                    int   oi = __shfl_xor_sync(0xffffffffu, bi, d);
                    if (ov > bv || (ov == bv && oi < bi)) { bv = ov; bi = oi; }
                }
                const int q = mt * 2 + hf;
                my_bt[q]  = bi;
                my_row[q] = wid * 32 + mt * 16 + hf * 8 + (lane >> 2);
            }
        }
    }

    int lpos[4];
    if (writer) {
        #pragma unroll
        for (int q = 0; q < 4; q++)
            lpos[q] = atomicAdd(&s_cnt[my_bt[q]], 1);
    }
    __syncthreads();
    if (tid < T_SZ) s_base[tid] = atomicAdd(&g_counts[tid], s_cnt[tid]);
    __syncthreads();
    if (writer) {
        #pragma unroll
        for (int q = 0; q < 4; q++) {
            const int r = row0 + my_row[q];
            g_rowlist[my_bt[q] * B_SZ + s_base[my_bt[q]] + lpos[q]] = r;
            if (write_idx) out_idx[r] = (float)my_bt[q];
        }
    }

    // ---- spill h to g_h (coalesced) ----
    #pragma unroll
    for (int i = 0; i < 32; i++) {
        const int e = tid + i * 256;
        const int row = e >> 6, c4 = e & 63;
        float4 v = *(const float4*)&hsm[row * HSTRIDE + c4 * 4];
        *(float4*)&g_h[(size_t)(row0 + row) * D_SZ + c4 * 4] = v;
    }
}

// ========================================================================
// Kernel 2: routed classifier (fp32 f32x2)
// ========================================================================
#define BM2 128
#define NT2 256
#define SMEM2 ((BM2 * D_SZ + D_SZ * C_SZ) * 4)

__global__ __launch_bounds__(NT2, 1)
void k2_classifier(const float* __restrict__ Wc,
                   const float* __restrict__ bc,
                   float* __restrict__ out)
{
    extern __shared__ float smf[];
    float* hs  = smf;
    float* wcs = smf + BM2 * D_SZ;
    __shared__ int rid_s[BM2];

    const int t    = blockIdx.y;
    const int cnt  = g_counts[t];
    const int base = blockIdx.x * BM2;
    if (base >= cnt) return;
    const int n = min(BM2, cnt - base);

    const int tid = threadIdx.x;
    if (tid < BM2) {
        int idx = (tid < n) ? tid : (n - 1);
        rid_s[tid] = g_rowlist[t * B_SZ + base + idx];
    }
    __syncthreads();

    for (int e = tid; e < BM2 * (D_SZ / 4); e += NT2) {
        const int lr = e >> 6;
        const int q  = e & 63;
        ((float4*)hs)[lr * (D_SZ / 4) + q] =
            ((const float4*)(g_h + (size_t)rid_s[lr] * D_SZ))[q];
    }
    const float4* wg = (const float4*)(Wc + (size_t)t * D_SZ * C_SZ);
    for (int e = tid; e < D_SZ * (C_SZ / 4); e += NT2)
        ((float4*)wcs)[e] = wg[e];
    __syncthreads();

    const int tx = tid & 15;
    const int ty = tid >> 4;

    unsigned long long acc[8][2];
    #pragma unroll
    for (int i = 0; i < 8; i++) { acc[i][0] = 0ull; acc[i][1] = 0ull; }

    #pragma unroll 4
    for (int k = 0; k < D_SZ; k++) {
        const unsigned long long* bq = (const unsigned long long*)&wcs[k * C_SZ + tx * 4];
        unsigned long long b0 = bq[0], b1 = bq[1];
        #pragma unroll
        for (int i = 0; i < 8; i++) {
            float av = hs[(ty * 8 + i) * D_SZ + k];
            unsigned long long a2 = pack2(av, av);
            ffma2(acc[i][0], a2, b0);
            ffma2(acc[i][1], a2, b1);
        }
    }

    float4 bcv = ((const float4*)(bc + t * C_SZ))[tx];
    #pragma unroll
    for (int i = 0; i < 8; i++) {
        const int lr = ty * 8 + i;
        if (lr < n) {
            float2 v0 = unpack2(acc[i][0]);
            float2 v1 = unpack2(acc[i][1]);
            float4 o = make_float4(v0.x + bcv.x, v0.y + bcv.y, v1.x + bcv.z, v1.y + bcv.w);
            *(float4*)(out + (size_t)rid_s[lr] * C_SZ + tx * 4) = o;
        }
    }
}

// ========================================================================
extern "C" void kernel_launch(void* const* d_in, const int* in_sizes, int n_in,
                              void* d_out, int out_size)
{
    const float* x    = (const float*)d_in[0];
    const float* Wp   = (const float*)d_in[1];
    const float* bp   = (const float*)d_in[2];
    const float* sigs = (const float*)d_in[3];
    const float* Wc   = (const float*)d_in[4];
    const float* bc   = (const float*)d_in[5];
    float* out = (float*)d_out;

    const int write_idx = (out_size >= B_SZ * C_SZ + B_SZ) ? 1 : 0;
    (void)in_sizes; (void)n_in;

    zero_counts_kernel<<<1, 32>>>();
    prep_B_kernel<<<NCHUNK, 256>>>(Wp);
    prep_Ws_kernel<<<104, 128>>>(Wp, bp, sigs);

    cudaFuncSetAttribute(k1_proj_route, cudaFuncAttributeMaxDynamicSharedMemorySize, SMEM1);
    k1_proj_route<<<NBLK, NT1, SMEM1>>>(x, bp, out + B_SZ * C_SZ, write_idx);

    cudaFuncSetAttribute(k2_classifier, cudaFuncAttributeMaxDynamicSharedMemorySize, SMEM2);
    dim3 g2(B_SZ / BM2, T_SZ);
    k2_classifier<<<g2, NT2, SMEM2>>>(Wc, bc, out);
}